// round 3
// baseline (speedup 1.0000x reference)
#include <cuda_runtime.h>

#define HH 256
#define WW 256
#define BB 8
#define IMG_PIX (HH*WW)          // 65536
#define NPIX (BB*IMG_PIX)        // 524288

#define TT 5                     // fused iterations per launch
#define RR 42                    // 32 + 2*TT
#define R2 (RR*RR)               // 1764
#define NL 6                     // launches (6*5 = 30)

static __device__ float  g_gray[2][NPIX];
static __device__ float  g_s[2][NPIX];
static __device__ float4 g_cst[NPIX];     // {dx, dy, rho_c+EPS, th}
static __device__ float  g_ig[NPIX];      // (grad>EPS) ? 1/grad : 0
static __device__ float2 g_u[2][NPIX];
static __device__ float4 g_p[2][NPIX];
static __device__ int    g_mn, g_mx;

__constant__ float GW[25] = {
    0.000874f, 0.006976f, 0.01386f,  0.006976f, 0.000874f,
    0.006976f, 0.0557f,   0.110656f, 0.0557f,   0.006976f,
    0.01386f,  0.110656f, 0.219833f, 0.110656f, 0.01386f,
    0.006976f, 0.0557f,   0.110656f, 0.0557f,   0.006976f,
    0.000874f, 0.006976f, 0.01386f,  0.006976f, 0.000874f
};

#define L_T    0.045f
#define THETA  0.3f
#define TAUT   0.8333333333333334f
#define EPSV   1e-12f

__device__ __forceinline__ float rsqrt_approx(float x){
    float y; asm("rsqrt.approx.f32 %0, %1;" : "=f"(y) : "f"(x)); return y;
}
__device__ __forceinline__ float rcp_approx(float x){
    float y; asm("rcp.approx.f32 %0, %1;" : "=f"(y) : "f"(x)); return y;
}

__global__ void k_init(){ g_mn = 0x7f7fffff; g_mx = 0; }

// gray conversion + global min/max reduction over BOTH images
__global__ __launch_bounds__(256) void k_gray(const float* __restrict__ x1,
                                              const float* __restrict__ x2)
{
    int idx = blockIdx.x*256 + threadIdx.x;     // < NPIX
    int b   = idx >> 16;
    int pix = idx & 65535;
    int o   = b*3*IMG_PIX + pix;
    float g1 = 0.114f*x1[o] + 0.587f*x1[o+IMG_PIX] + 0.299f*x1[o+2*IMG_PIX];
    float g2 = 0.114f*x2[o] + 0.587f*x2[o+IMG_PIX] + 0.299f*x2[o+2*IMG_PIX];
    g_gray[0][idx] = g1;
    g_gray[1][idx] = g2;
    float mn = fminf(g1, g2), mx = fmaxf(g1, g2);
    #pragma unroll
    for (int off = 16; off; off >>= 1){
        mn = fminf(mn, __shfl_xor_sync(0xffffffffu, mn, off));
        mx = fmaxf(mx, __shfl_xor_sync(0xffffffffu, mx, off));
    }
    __shared__ float smn[8], smx[8];
    int lane = threadIdx.x & 31, w = threadIdx.x >> 5;
    if (!lane){ smn[w] = mn; smx[w] = mx; }
    __syncthreads();
    if (threadIdx.x == 0){
        #pragma unroll
        for (int i = 1; i < 8; i++){ mn = fminf(mn, smn[i]); mx = fmaxf(mx, smx[i]); }
        atomicMin(&g_mn, __float_as_int(mn));   // all values >= 0: int order == float order
        atomicMax(&g_mx, __float_as_int(mx));
    }
}

// normalize + 5x5 gaussian (zero SAME padding)
__global__ __launch_bounds__(256) void k_smooth()
{
    int img = blockIdx.z >> 3;
    int b   = blockIdx.z & 7;
    const float* gsrc = g_gray[img] + b*IMG_PIX;
    float mn = __int_as_float(g_mn);
    float mx = __int_as_float(g_mx);
    float scale = 255.0f / (mx - mn);
    __shared__ float sn[36*36];
    int tx0 = blockIdx.x*32, ty0 = blockIdx.y*32;
    int tid = threadIdx.x;
    for (int idx = tid; idx < 36*36; idx += 256){
        int li = idx/36, lj = idx - li*36;
        int gi = ty0 + li - 2, gj = tx0 + lj - 2;
        float v = 0.f;
        if ((unsigned)gi < HH && (unsigned)gj < WW) v = (gsrc[gi*WW+gj] - mn)*scale;
        sn[idx] = v;
    }
    __syncthreads();
    int lj = tid & 31, li0 = tid >> 5;
    #pragma unroll
    for (int r = 0; r < 4; r++){
        int li = li0 + r*8;
        float acc = 0.f;
        #pragma unroll
        for (int a = 0; a < 5; a++)
            #pragma unroll
            for (int c = 0; c < 5; c++)
                acc += GW[a*5+c]*sn[(li+a)*36 + lj + c];
        g_s[img][b*IMG_PIX + (ty0+li)*WW + tx0+lj] = acc;
    }
}

// centered grad of s2, per-pixel constants, zero-init state
__global__ __launch_bounds__(256) void k_prep()
{
    int idx = blockIdx.x*256 + threadIdx.x;
    int b = idx >> 16, pix = idx & 65535;
    int i = pix >> 8, j = pix & 255;
    const float* s2 = g_s[1] + b*IMG_PIX;
    float c  = s2[pix];
    float xr = s2[i*WW + min(j+1, WW-1)];
    float xl = s2[i*WW + max(j-1, 0)];
    float yd = s2[min(i+1, HH-1)*WW + j];
    float yu = s2[max(i-1, 0)*WW + j];
    float dx = 0.5f*(xr - xl);
    float dy = 0.5f*(yd - yu);
    float grad = dx*dx + dy*dy + EPSV;
    float rho_c = c - g_s[0][idx] + EPSV;
    g_cst[idx] = make_float4(dx, dy, rho_c, L_T*grad);
    g_ig[idx]  = (grad > EPSV) ? (1.0f/grad) : 0.0f;
    g_u[0][idx] = make_float2(0.f, 0.f);
    g_p[0][idx] = make_float4(0.f, 0.f, 0.f, 0.f);
}

// Fused block of TT TV-L1 iterations on a 32x32 tile with TT-halo.
// State (u,p) updated in place in smem; valid region shrinks 1/side/iter.
// Invariant: p11/p21 are identically 0 on the last image column and p12/p22
// on the last image row (never read by divergence; forced by fwd-grad zeroing)
// -> divergence needs NO boundary predicates with a zero halo.
__global__ __launch_bounds__(256, 2) void k_fused(int L, float* __restrict__ out)
{
    extern __shared__ char smemraw[];
    float4* sp   = (float4*)smemraw;              // R2 float4
    float4* scst = sp + R2;                       // R2 float4
    float2* su   = (float2*)(scst + R2);          // R2 float2
    float*  sig  = (float*)(su + R2);             // R2 float

    const int tx0 = blockIdx.x*32, ty0 = blockIdx.y*32, b = blockIdx.z;
    const int base = b*IMG_PIX;
    const int tid  = threadIdx.x;
    const int s = L & 1;
    const float4* __restrict__ p_in = g_p[s];
    const float2* __restrict__ u_in = g_u[s];
    float4* __restrict__ p_out = g_p[s^1];
    float2* __restrict__ u_out = g_u[s^1];
    const bool lastL = (L == NL-1);

    // stage region (zero pad outside image)
    for (int idx = tid; idx < R2; idx += 256){
        int li = idx / RR, lj = idx - li*RR;
        int gi = ty0 + li - TT, gj = tx0 + lj - TT;
        bool in = ((unsigned)gi < HH) && ((unsigned)gj < WW);
        int g = base + gi*WW + gj;
        sp[idx]   = in ? p_in[g]  : make_float4(0.f,0.f,0.f,0.f);
        su[idx]   = in ? u_in[g]  : make_float2(0.f,0.f);
        scst[idx] = in ? g_cst[g] : make_float4(0.f,0.f,0.f,0.f);
        sig[idx]  = in ? g_ig[g]  : 0.f;
    }
    __syncthreads();

    #pragma unroll
    for (int t = 0; t < TT; ++t){
        const int lo  = t + 1;
        const int hiU = RR - 1 - t;
        const int hiP = RR - 2 - t;

        // ---- u update (in place) ----
        for (int idx = tid; idx < R2; idx += 256){
            int li = idx / RR, lj = idx - li*RR;
            if (li < lo | li > hiU | lj < lo | lj > hiU) continue;
            int gi = ty0 + li - TT, gj = tx0 + lj - TT;
            if (((unsigned)gi >= HH) | ((unsigned)gj >= WW)) continue;
            float4 c = scst[idx];
            float2 u = su[idx];
            float rho = c.z + c.x*u.x + c.y*u.y;
            float coef = (rho < -c.w) ? L_T : ((rho > c.w) ? -L_T : -rho*sig[idx]);
            float4 pc = sp[idx];
            float4 pl = sp[idx-1];
            float4 pu = sp[idx-RR];
            float d1 = pc.x - pl.x + pc.y - pu.y;
            float d2 = pc.z - pl.z + pc.w - pu.w;
            float2 un;
            un.x = fmaf(coef, c.x, u.x) + THETA*d1;
            un.y = fmaf(coef, c.y, u.y) + THETA*d2;
            su[idx] = un;
            if (lastL && t == TT-1){
                // rho uses u BEFORE the final update (scan carry semantics)
                if (li >= TT && li < TT+32 && lj >= TT && lj < TT+32)
                    out[b*3*IMG_PIX + 2*IMG_PIX + gi*WW + gj] = rho;
            }
        }
        __syncthreads();

        // ---- p update (in place) ----
        for (int idx = tid; idx < R2; idx += 256){
            int li = idx / RR, lj = idx - li*RR;
            if (li < lo | li > hiP | lj < lo | lj > hiP) continue;
            int gi = ty0 + li - TT, gj = tx0 + lj - TT;
            if (((unsigned)gi >= HH) | ((unsigned)gj >= WW)) continue;
            float2 uc = su[idx];
            float2 ur = su[idx+1];
            float2 ud = su[idx+RR];
            bool bx = (gj == WW-1), by = (gi == HH-1);
            float u1x = bx ? 0.f : ur.x - uc.x;
            float u2x = bx ? 0.f : ur.y - uc.y;
            float u1y = by ? 0.f : ud.x - uc.x;
            float u2y = by ? 0.f : ud.y - uc.y;
            float s1 = u1x*u1x + u1y*u1y + EPSV;
            float s2 = u2x*u2x + u2y*u2y + EPSV;
            float ng1 = 1.f + TAUT*(s1*rsqrt_approx(s1));
            float ng2 = 1.f + TAUT*(s2*rsqrt_approx(s2));
            float r1 = rcp_approx(ng1), r2 = rcp_approx(ng2);
            float4 p = sp[idx];
            sp[idx] = make_float4((p.x + TAUT*u1x)*r1, (p.y + TAUT*u1y)*r1,
                                  (p.z + TAUT*u2x)*r2, (p.w + TAUT*u2y)*r2);
        }
        __syncthreads();
    }

    // ---- store tile interior ----
    for (int idx = tid; idx < 32*32; idx += 256){
        int li = idx >> 5, lj = idx & 31;
        int gi = ty0 + li, gj = tx0 + lj;
        int g = base + gi*WW + gj;
        int sidx = (li+TT)*RR + (lj+TT);
        p_out[g] = sp[sidx];
        float2 uv = su[sidx];
        u_out[g] = uv;
        if (lastL){
            int ob = b*3*IMG_PIX + gi*WW + gj;
            out[ob]           = uv.x;
            out[ob + IMG_PIX] = uv.y;
        }
    }
}

#define SMEM_BYTES (R2*(16+16+8+4))   // 77616

extern "C" void kernel_launch(void* const* d_in, const int* in_sizes, int n_in,
                              void* d_out, int out_size)
{
    const float* x1 = (const float*)d_in[0];
    const float* x2 = (const float*)d_in[1];
    float* out = (float*)d_out;

    cudaFuncSetAttribute(k_fused, cudaFuncAttributeMaxDynamicSharedMemorySize,
                         SMEM_BYTES);

    k_init<<<1, 1>>>();
    k_gray<<<NPIX/256, 256>>>(x1, x2);
    dim3 gB(8, 8, 16);
    k_smooth<<<gB, 256>>>();
    k_prep<<<NPIX/256, 256>>>();
    dim3 gI(8, 8, 8);
    for (int L = 0; L < NL; ++L)
        k_fused<<<gI, 256, SMEM_BYTES>>>(L, out);
}

// round 5
// speedup vs baseline: 2.2958x; 2.2958x over previous
#include <cuda_runtime.h>

#define HH 256
#define WW 256
#define BB 8
#define IMG_PIX (HH*WW)          // 65536
#define NPIX (BB*IMG_PIX)        // 524288

static __device__ float  g_gray[2][NPIX];
static __device__ float  g_s[2][NPIX];
static __device__ float4 g_cst[NPIX];     // {dx, dy, rho_c+EPS, th}
static __device__ float  g_ig[NPIX];      // (grad>EPS) ? 1/grad : 0
static __device__ float2 g_u[2][NPIX];
static __device__ float4 g_p[2][NPIX];
static __device__ int    g_mn, g_mx;

__constant__ float GW[25] = {
    0.000874f, 0.006976f, 0.01386f,  0.006976f, 0.000874f,
    0.006976f, 0.0557f,   0.110656f, 0.0557f,   0.006976f,
    0.01386f,  0.110656f, 0.219833f, 0.110656f, 0.01386f,
    0.006976f, 0.0557f,   0.110656f, 0.0557f,   0.006976f,
    0.000874f, 0.006976f, 0.01386f,  0.006976f, 0.000874f
};

#define L_T    0.045f
#define THETA  0.3f
#define TAUT   0.8333333333333334f
#define EPSV   1e-12f

__device__ __forceinline__ float rsqrt_approx(float x){
    float y; asm("rsqrt.approx.f32 %0, %1;" : "=f"(y) : "f"(x)); return y;
}
__device__ __forceinline__ float rcp_approx(float x){
    float y; asm("rcp.approx.f32 %0, %1;" : "=f"(y) : "f"(x)); return y;
}

__global__ void k_init(){ g_mn = 0x7f7fffff; g_mx = 0; }

// gray conversion + global min/max reduction over BOTH images
__global__ __launch_bounds__(256) void k_gray(const float* __restrict__ x1,
                                              const float* __restrict__ x2)
{
    int idx = blockIdx.x*256 + threadIdx.x;     // < NPIX
    int b   = idx >> 16;
    int pix = idx & 65535;
    int o   = b*3*IMG_PIX + pix;
    float g1 = 0.114f*x1[o] + 0.587f*x1[o+IMG_PIX] + 0.299f*x1[o+2*IMG_PIX];
    float g2 = 0.114f*x2[o] + 0.587f*x2[o+IMG_PIX] + 0.299f*x2[o+2*IMG_PIX];
    g_gray[0][idx] = g1;
    g_gray[1][idx] = g2;
    float mn = fminf(g1, g2), mx = fmaxf(g1, g2);
    #pragma unroll
    for (int off = 16; off; off >>= 1){
        mn = fminf(mn, __shfl_xor_sync(0xffffffffu, mn, off));
        mx = fmaxf(mx, __shfl_xor_sync(0xffffffffu, mx, off));
    }
    __shared__ float smn[8], smx[8];
    int lane = threadIdx.x & 31, w = threadIdx.x >> 5;
    if (!lane){ smn[w] = mn; smx[w] = mx; }
    __syncthreads();
    if (threadIdx.x == 0){
        #pragma unroll
        for (int i = 1; i < 8; i++){ mn = fminf(mn, smn[i]); mx = fmaxf(mx, smx[i]); }
        atomicMin(&g_mn, __float_as_int(mn));   // all values >= 0: int order == float order
        atomicMax(&g_mx, __float_as_int(mx));
    }
}

// normalize + 5x5 gaussian (zero SAME padding)
__global__ __launch_bounds__(256) void k_smooth()
{
    int img = blockIdx.z >> 3;
    int b   = blockIdx.z & 7;
    const float* gsrc = g_gray[img] + b*IMG_PIX;
    float mn = __int_as_float(g_mn);
    float mx = __int_as_float(g_mx);
    float scale = 255.0f / (mx - mn);
    __shared__ float sn[36*36];
    int tx0 = blockIdx.x*32, ty0 = blockIdx.y*32;
    int tid = threadIdx.x;
    for (int idx = tid; idx < 36*36; idx += 256){
        int li = idx/36, lj = idx - li*36;
        int gi = ty0 + li - 2, gj = tx0 + lj - 2;
        float v = 0.f;
        if ((unsigned)gi < HH && (unsigned)gj < WW) v = (gsrc[gi*WW+gj] - mn)*scale;
        sn[idx] = v;
    }
    __syncthreads();
    int lj = tid & 31, li0 = tid >> 5;
    #pragma unroll
    for (int r = 0; r < 4; r++){
        int li = li0 + r*8;
        float acc = 0.f;
        #pragma unroll
        for (int a = 0; a < 5; a++)
            #pragma unroll
            for (int c = 0; c < 5; c++)
                acc += GW[a*5+c]*sn[(li+a)*36 + lj + c];
        g_s[img][b*IMG_PIX + (ty0+li)*WW + tx0+lj] = acc;
    }
}

// centered grad of s2, per-pixel constants, zero-init state
__global__ __launch_bounds__(256) void k_prep()
{
    int idx = blockIdx.x*256 + threadIdx.x;
    int b = idx >> 16, pix = idx & 65535;
    int i = pix >> 8, j = pix & 255;
    const float* s2 = g_s[1] + b*IMG_PIX;
    float c  = s2[pix];
    float xr = s2[i*WW + min(j+1, WW-1)];
    float xl = s2[i*WW + max(j-1, 0)];
    float yd = s2[min(i+1, HH-1)*WW + j];
    float yu = s2[max(i-1, 0)*WW + j];
    float dx = 0.5f*(xr - xl);
    float dy = 0.5f*(yd - yu);
    float grad = dx*dx + dy*dy + EPSV;
    float rho_c = c - g_s[0][idx] + EPSV;
    g_cst[idx] = make_float4(dx, dy, rho_c, L_T*grad);
    g_ig[idx]  = (grad > EPSV) ? (1.0f/grad) : 0.0f;
    g_u[0][idx] = make_float2(0.f, 0.f);
    g_p[0][idx] = make_float4(0.f, 0.f, 0.f, 0.f);
}

// u-update body. Valid only for in-image (gi,gj).
// Uses the invariant: p11/p21 == 0 on the last image column and p12/p22 == 0
// on the last image row (maintained by the p-pass boundary selects), so the
// divergence needs no right/bottom predicates; only up/left loads are guarded.
__device__ __forceinline__ float2 u_update(const float4* __restrict__ p_in,
                                           const float2* __restrict__ u_in,
                                           int g, int gi, int gj,
                                           float4& pc_out, float& rho_out)
{
    float4 c  = __ldg(&g_cst[g]);
    float  ig = __ldg(&g_ig[g]);
    float2 u  = __ldg(&u_in[g]);
    float4 pc = __ldg(&p_in[g]);
    float4 pl = (gj > 0) ? __ldg(&p_in[g-1])  : make_float4(0.f,0.f,0.f,0.f);
    float4 pu = (gi > 0) ? __ldg(&p_in[g-WW]) : make_float4(0.f,0.f,0.f,0.f);
    pc_out = pc;
    float rho = c.z + c.x*u.x + c.y*u.y;
    rho_out = rho;
    float coef = (rho < -c.w) ? L_T : ((rho > c.w) ? -L_T : -rho*ig);
    float d1 = pc.x - pl.x + pc.y - pu.y;
    float d2 = pc.z - pl.z + pc.w - pu.w;
    float2 un;
    un.x = fmaf(coef, c.x, u.x) + THETA*d1;
    un.y = fmaf(coef, c.y, u.y) + THETA*d2;
    return un;
}

// One TV-L1 iteration. 32x32 tile, 256 threads, 4 pixels/thread.
// u_new exchanged through smem (33x33 incl. right/down halo); everything else
// read straight from global (L1/L2 resident).
__global__ __launch_bounds__(256) void k_iter(int s, int last, float* __restrict__ out)
{
    __shared__ float2 su[33*33];

    const int tx = threadIdx.x & 31, ty = threadIdx.x >> 5;
    const int tx0 = blockIdx.x*32, ty0 = blockIdx.y*32, b = blockIdx.z;
    const int base = b*IMG_PIX;
    const float4* __restrict__ p_in = g_p[s];
    const float2* __restrict__ u_in = g_u[s];
    float4* __restrict__ p_out = g_p[s^1];
    float2* __restrict__ u_out = g_u[s^1];

    float4 pc_r[4];

    // ---- u-pass: own 4 pixels ----
    #pragma unroll
    for (int r = 0; r < 4; r++){
        int li = r*8 + ty;
        int gi = ty0 + li, gj = tx0 + tx;
        int g = base + gi*WW + gj;
        float rho;
        float2 un = u_update(p_in, u_in, g, gi, gj, pc_r[r], rho);
        su[li*33 + tx] = un;
        if (last) out[b*3*IMG_PIX + 2*IMG_PIX + gi*WW + gj] = rho;
    }
    // ---- u-pass halo: right column (by warp 0) and bottom row (warp 1) ----
    if (ty == 0){
        int gi = ty0 + tx, gj = tx0 + 32;
        if (gj < WW){
            int g = base + gi*WW + gj;
            float4 dummy; float rho;
            su[tx*33 + 32] = u_update(p_in, u_in, g, gi, gj, dummy, rho);
        }
    } else if (ty == 1){
        int gi = ty0 + 32, gj = tx0 + tx;
        if (gi < HH){
            int g = base + gi*WW + gj;
            float4 dummy; float rho;
            su[32*33 + tx] = u_update(p_in, u_in, g, gi, gj, dummy, rho);
        }
    }
    __syncthreads();

    // ---- p-pass: own 4 pixels ----
    #pragma unroll
    for (int r = 0; r < 4; r++){
        int li = r*8 + ty;
        int gi = ty0 + li, gj = tx0 + tx;
        int g = base + gi*WW + gj;
        float2 uc = su[li*33 + tx];
        float2 ur = su[li*33 + tx + 1];
        float2 ud = su[(li+1)*33 + tx];
        bool bx = (gj == WW-1), by = (gi == HH-1);
        float u1x = bx ? 0.f : ur.x - uc.x;
        float u2x = bx ? 0.f : ur.y - uc.y;
        float u1y = by ? 0.f : ud.x - uc.x;
        float u2y = by ? 0.f : ud.y - uc.y;
        float s1 = u1x*u1x + u1y*u1y + EPSV;
        float s2 = u2x*u2x + u2y*u2y + EPSV;
        float ng1 = 1.f + TAUT*(s1*rsqrt_approx(s1));
        float ng2 = 1.f + TAUT*(s2*rsqrt_approx(s2));
        float r1 = rcp_approx(ng1), r2 = rcp_approx(ng2);
        float4 p = pc_r[r];
        if (last){
            int ob = b*3*IMG_PIX + gi*WW + gj;
            out[ob]           = uc.x;
            out[ob + IMG_PIX] = uc.y;
        } else {
            p_out[g] = make_float4((p.x + TAUT*u1x)*r1, (p.y + TAUT*u1y)*r1,
                                   (p.z + TAUT*u2x)*r2, (p.w + TAUT*u2y)*r2);
            u_out[g] = uc;
        }
    }
}

extern "C" void kernel_launch(void* const* d_in, const int* in_sizes, int n_in,
                              void* d_out, int out_size)
{
    const float* x1 = (const float*)d_in[0];
    const float* x2 = (const float*)d_in[1];
    float* out = (float*)d_out;

    k_init<<<1, 1>>>();
    k_gray<<<NPIX/256, 256>>>(x1, x2);
    dim3 gB(8, 8, 16);
    k_smooth<<<gB, 256>>>();
    k_prep<<<NPIX/256, 256>>>();
    dim3 gI(8, 8, 8);
    for (int it = 0; it < 30; ++it)
        k_iter<<<gI, 256>>>(it & 1, it == 29, out);
}